// round 9
// baseline (speedup 1.0000x reference)
#include <cuda_runtime.h>
#include <cstdint>
#include <cstddef>

#define BMAX 32768

// ---------------- device scratch (uninitialized globals; no allocations) ----------------
__device__ float g_x[BMAX * 64];              // tanh features of cond MLP
__device__ float g_cond[3 * BMAX * 256];      // [0]=b_mod, [1]=c_mod, [2]=w_scale
__device__ float g_v[BMAX * 256];             // model visible state (0/1 floats)
__device__ float g_h[BMAX * 256];             // h * w_scale
__device__ float g_t[BMAX * 256];             // v @ W scratch for free energy
__device__ float g_WT[256 * 256];             // W transposed
__device__ float g_P[64 * 768];               // combined cond-param weights, [k][n]
__device__ float g_pb[768];                   // combined cond-param bias
__device__ float g_Wsum[256];                 // W.sum(axis=0)
__device__ float g_part[BMAX / 4];            // block partial sums (2 * B/8)

// ---------------- packed f32x2 FMA (Blackwell) ----------------
#define FFMA2_(d, a, b) \
    asm("fma.rn.f32x2 %0, %1, %2, %0;" : "+l"(d) : "l"(a), "l"(b))
#define PACK2_DUP_(d, s) \
    asm("mov.b64 %0, {%1, %1};" : "=l"(d) : "f"(s))
#define UNPACK2_(lo, hi, s) \
    asm("mov.b64 {%0, %1}, %2;" : "=f"(lo), "=f"(hi) : "l"(s))

// ---------------- threefry2x32-20 (exact JAX PRNG) ----------------
__host__ __device__ inline uint32_t rotl32(uint32_t v, int d) {
    return (v << d) | (v >> (32 - d));
}

__host__ __device__ inline void tf2x32(uint32_t k0, uint32_t k1, uint32_t& x0, uint32_t& x1) {
    uint32_t ks2 = k0 ^ k1 ^ 0x1BD11BDAu;
    x0 += k0; x1 += k1;
    x0 += x1; x1 = rotl32(x1, 13); x1 ^= x0;
    x0 += x1; x1 = rotl32(x1, 15); x1 ^= x0;
    x0 += x1; x1 = rotl32(x1, 26); x1 ^= x0;
    x0 += x1; x1 = rotl32(x1,  6); x1 ^= x0;
    x0 += k1;  x1 += ks2 + 1u;
    x0 += x1; x1 = rotl32(x1, 17); x1 ^= x0;
    x0 += x1; x1 = rotl32(x1, 29); x1 ^= x0;
    x0 += x1; x1 = rotl32(x1, 16); x1 ^= x0;
    x0 += x1; x1 = rotl32(x1, 24); x1 ^= x0;
    x0 += ks2; x1 += k0 + 2u;
    x0 += x1; x1 = rotl32(x1, 13); x1 ^= x0;
    x0 += x1; x1 = rotl32(x1, 15); x1 ^= x0;
    x0 += x1; x1 = rotl32(x1, 26); x1 ^= x0;
    x0 += x1; x1 = rotl32(x1,  6); x1 ^= x0;
    x0 += k0;  x1 += k1 + 3u;
    x0 += x1; x1 = rotl32(x1, 17); x1 ^= x0;
    x0 += x1; x1 = rotl32(x1, 29); x1 ^= x0;
    x0 += x1; x1 = rotl32(x1, 16); x1 ^= x0;
    x0 += x1; x1 = rotl32(x1, 24); x1 ^= x0;
    x0 += k1;  x1 += ks2 + 4u;
    x0 += x1; x1 = rotl32(x1, 13); x1 ^= x0;
    x0 += x1; x1 = rotl32(x1, 15); x1 ^= x0;
    x0 += x1; x1 = rotl32(x1, 26); x1 ^= x0;
    x0 += x1; x1 = rotl32(x1,  6); x1 ^= x0;
    x0 += ks2; x1 += k0 + 5u;
}

// Single-element uniform (used where pairing is awkward)
__device__ inline float tf_uniform(uint32_t k0, uint32_t k1, uint32_t f, uint32_t half) {
    uint32_t sec = (f >= half) ? 1u : 0u;
    uint32_t lane = sec ? (f - half) : f;
    uint32_t x0 = lane, x1 = lane + half;
    tf2x32(k0, k1, x0, x1);
    uint32_t bits = sec ? x1 : x0;
    return __uint_as_float((bits >> 9) | 0x3f800000u) - 1.0f;
}

// Paired uniform: one cipher yields u(f) and u(f+half) for f < half.
__device__ inline void tf_uniform2(uint32_t k0, uint32_t k1, uint32_t f, uint32_t half,
                                   float& u0, float& u1) {
    uint32_t x0 = f, x1 = f + half;
    tf2x32(k0, k1, x0, x1);
    u0 = __uint_as_float((x0 >> 9) | 0x3f800000u) - 1.0f;
    u1 = __uint_as_float((x1 >> 9) | 0x3f800000u) - 1.0f;
}

__device__ inline float sigmoidf_(float x) {
    float e = expf(-fabsf(x));
    float s = 1.0f / (1.0f + e);
    return (x >= 0.0f) ? s : (1.0f - s);
}

__device__ inline float softplusf_(float x) {
    return fmaxf(x, 0.0f) + log1pf(expf(-fabsf(x)));
}

// ---------------- prep: WT, Wsum, combined cond-param weights ----------------
__global__ void __launch_bounds__(256) prep_kernel(
    const float* __restrict__ W, const float* __restrict__ b, const float* __restrict__ c,
    const float* __restrict__ fc2w, const float* __restrict__ fc2b,
    float* __restrict__ WT, float* __restrict__ P, float* __restrict__ pb,
    float* __restrict__ Wsum)
{
    int idx = blockIdx.x * blockDim.x + threadIdx.x;
    int stride = gridDim.x * blockDim.x;
    for (int i = idx; i < 256 * 256; i += stride) {
        int k = i >> 8, cc = i & 255;
        WT[k * 256 + cc] = W[cc * 256 + k];
    }
    for (int i = idx; i < 64 * 768; i += stride) {
        int k = i / 768, n = i % 768;
        float val;
        if (n < 256)      val = b[n] * fc2w[n * 64 + k] + fc2w[(256 + n) * 64 + k];
        else if (n < 512) { int j = n - 256; val = c[j] * fc2w[(512 + j) * 64 + k] + fc2w[(768 + j) * 64 + k]; }
        else              { int j = n - 512; val = fc2w[(1024 + j) * 64 + k]; }
        P[k * 768 + n] = val;
    }
    for (int i = idx; i < 768; i += stride) {
        float val;
        if (i < 256)      val = b[i] * (1.0f + fc2b[i]) + fc2b[256 + i];
        else if (i < 512) { int j = i - 256; val = c[j] * (1.0f + fc2b[512 + j]) + fc2b[768 + j]; }
        else              { int j = i - 512; val = fc2b[1024 + j]; }
        pb[i] = val;
    }
    for (int i = idx; i < 256; i += stride) {
        float s = 0.0f;
        for (int rr = 0; rr < 256; rr++) s += W[rr * 256 + i];
        Wsum[i] = s;
    }
}

// ---------------- x = tanh(cond @ fc1_w.T + fc1_b), [B,64]x[64,64] ----------------
__global__ void __launch_bounds__(256) cond_fc1_kernel(
    const float* __restrict__ cond, const float* __restrict__ fc1w,
    const float* __restrict__ fc1b, float* __restrict__ xout)
{
    __shared__ float Cs[64][65];
    __shared__ float Ws[64][65];
    int t = threadIdx.x;
    int r0 = blockIdx.x * 64;
#pragma unroll
    for (int l = 0; l < 4; l++) {
        int id = t + l * 256;
        int j = id >> 4, k4 = (id & 15) << 2;
        float4 w = *(const float4*)(fc1w + j * 64 + k4);
        Ws[k4 + 0][j] = w.x; Ws[k4 + 1][j] = w.y; Ws[k4 + 2][j] = w.z; Ws[k4 + 3][j] = w.w;
    }
#pragma unroll
    for (int l = 0; l < 4; l++) {
        int id = t + l * 256;
        int i = id >> 4, k4 = (id & 15) << 2;
        float4 v = *(const float4*)(cond + (size_t)(r0 + i) * 64 + k4);
        Cs[i][k4 + 0] = v.x; Cs[i][k4 + 1] = v.y; Cs[i][k4 + 2] = v.z; Cs[i][k4 + 3] = v.w;
    }
    __syncthreads();
    int tx = t & 15, ty = t >> 4;
    float acc[4][4];
#pragma unroll
    for (int i = 0; i < 4; i++)
#pragma unroll
        for (int j = 0; j < 4; j++) acc[i][j] = 0.0f;
#pragma unroll 8
    for (int k = 0; k < 64; k++) {
        float a[4], bv[4];
#pragma unroll
        for (int i = 0; i < 4; i++) a[i] = Cs[ty * 4 + i][k];
#pragma unroll
        for (int j = 0; j < 4; j++) bv[j] = Ws[k][tx * 4 + j];
#pragma unroll
        for (int i = 0; i < 4; i++)
#pragma unroll
            for (int j = 0; j < 4; j++) acc[i][j] = fmaf(a[i], bv[j], acc[i][j]);
    }
#pragma unroll
    for (int i = 0; i < 4; i++) {
        int r = r0 + ty * 4 + i;
#pragma unroll
        for (int j = 0; j < 4; j++) {
            int jj = tx * 4 + j;
            xout[(size_t)r * 64 + jj] = tanhf(acc[i][j] + fc1b[jj]);
        }
    }
}

// ---------------- v_model init: noise rows (threefry) + copy of v_data ----------------
__global__ void __launch_bounds__(256) init_v_kernel(
    const float* __restrict__ vdata, float* __restrict__ v,
    int B, int n_noise, uint32_t k0, uint32_t k1)
{
    int total = B * 256;
    uint32_t half = (uint32_t)(n_noise * 128);
    for (int idx = blockIdx.x * blockDim.x + threadIdx.x; idx < total;
         idx += gridDim.x * blockDim.x) {
        int r = idx >> 8;
        float val;
        if (r < n_noise) {
            float u = tf_uniform(k0, k1, (uint32_t)idx, half);
            val = (u < 0.5f) ? 1.0f : 0.0f;
        } else {
            val = vdata[idx];
        }
        v[idx] = val;
    }
}

// ---------------- 128x128x16 SGEMM, f32x2, split-row tiles, paired RNG ----------------
// Tile rows 0..63 map to global rows by*64+r (low half of M), rows 64..127 map to
// M/2 + by*64 + r (high half). Each thread owns matching low/high rows so one
// threefry cipher serves both elements of a JAX-uniform pair.
// Double-buffered smem, one __syncthreads per K-tile. Bs pre-duplicated to f32x2.
// MODE 0: cond params (N=768); MODE 1: h-sample (stores h*w_scale);
// MODE 2: v-sample; MODE 3: plain store.
#define SGEMM_SMEM (2 * 16 * 132 * 4 + 2 * 16 * 128 * 8)

template <int MODE>
__global__ void __launch_bounds__(256, 2) sgemm_kernel(
    const float* __restrict__ A, const float* __restrict__ Bm,
    float* __restrict__ out,
    const float* __restrict__ e0, const float* __restrict__ e1,
    int M, int N, int K,
    uint32_t rk0, uint32_t rk1, uint32_t half)
{
    extern __shared__ char smem_raw[];
    typedef float AsT[16][132];
    typedef unsigned long long BsT[16][128];
    AsT* As = (AsT*)smem_raw;                               // As[0..1][k][row]
    BsT* Bs2 = (BsT*)(smem_raw + 2 * 16 * 132 * 4);         // Bs2[0..1][k][n], dup f32x2

    const int t = threadIdx.x;
    const int tx = t & 15, ty = t >> 4;
    const int bx = blockIdx.x, by = blockIdx.y;
    const int Mh = M >> 1;
    const float* Bb = Bm + (size_t)bx * 128;

    // A-load lanes: thread loads row lrow (low half) and 64+lrow (high half)
    const int lrow = t >> 2;
    const int lc4 = (t & 3) << 2;
    const float* Arow0 = A + (size_t)(by * 64 + lrow) * K + lc4;
    const float* Arow1 = A + (size_t)(Mh + by * 64 + lrow) * K + lc4;
    // B-load lanes
    const int bkk = t >> 5;
    const int bn4 = (t & 31) << 2;

    unsigned long long acc2[4][8];
#pragma unroll
    for (int i = 0; i < 4; i++)
#pragma unroll
        for (int j = 0; j < 8; j++) acc2[i][j] = 0ull;

    float4 ra0 = *(const float4*)(Arow0);
    float4 ra1 = *(const float4*)(Arow1);
    float4 rb0 = *(const float4*)(Bb + (size_t)bkk * N + bn4);
    float4 rb1 = *(const float4*)(Bb + (size_t)(bkk + 8) * N + bn4);

    auto stage = [&](int buf) {
        As[buf][lc4 + 0][lrow] = ra0.x; As[buf][lc4 + 1][lrow] = ra0.y;
        As[buf][lc4 + 2][lrow] = ra0.z; As[buf][lc4 + 3][lrow] = ra0.w;
        As[buf][lc4 + 0][64 + lrow] = ra1.x; As[buf][lc4 + 1][64 + lrow] = ra1.y;
        As[buf][lc4 + 2][64 + lrow] = ra1.z; As[buf][lc4 + 3][64 + lrow] = ra1.w;
        unsigned long long d;
        PACK2_DUP_(d, rb0.x); Bs2[buf][bkk][bn4 + 0] = d;
        PACK2_DUP_(d, rb0.y); Bs2[buf][bkk][bn4 + 1] = d;
        PACK2_DUP_(d, rb0.z); Bs2[buf][bkk][bn4 + 2] = d;
        PACK2_DUP_(d, rb0.w); Bs2[buf][bkk][bn4 + 3] = d;
        PACK2_DUP_(d, rb1.x); Bs2[buf][bkk + 8][bn4 + 0] = d;
        PACK2_DUP_(d, rb1.y); Bs2[buf][bkk + 8][bn4 + 1] = d;
        PACK2_DUP_(d, rb1.z); Bs2[buf][bkk + 8][bn4 + 2] = d;
        PACK2_DUP_(d, rb1.w); Bs2[buf][bkk + 8][bn4 + 3] = d;
    };

    const int T = K >> 4;
    stage(0);
    __syncthreads();

    for (int tile = 0; tile < T; tile++) {
        const int buf = tile & 1;
        if (tile + 1 < T) {
            const int ko = (tile + 1) * 16;
            ra0 = *(const float4*)(Arow0 + ko);
            ra1 = *(const float4*)(Arow1 + ko);
            rb0 = *(const float4*)(Bb + (size_t)(ko + bkk) * N + bn4);
            rb1 = *(const float4*)(Bb + (size_t)(ko + bkk + 8) * N + bn4);
        }
#pragma unroll
        for (int kk = 0; kk < 16; kk++) {
            unsigned long long a2[4];
            a2[0] = *(const unsigned long long*)&As[buf][kk][ty * 4];
            a2[1] = *(const unsigned long long*)&As[buf][kk][ty * 4 + 2];
            a2[2] = *(const unsigned long long*)&As[buf][kk][64 + ty * 4];
            a2[3] = *(const unsigned long long*)&As[buf][kk][64 + ty * 4 + 2];
#pragma unroll
            for (int j = 0; j < 8; j++) {
                unsigned long long b2 = Bs2[buf][kk][tx + 16 * j];
                FFMA2_(acc2[0][j], a2[0], b2);
                FFMA2_(acc2[1][j], a2[1], b2);
                FFMA2_(acc2[2][j], a2[2], b2);
                FFMA2_(acc2[3][j], a2[3], b2);
            }
        }
        if (tile + 1 < T) {
            stage(buf ^ 1);
            __syncthreads();
        }
    }

    // epilogue: thread owns low rows (by*64+ty*4+q) and high rows (Mh + same), q=0..3
#pragma unroll
    for (int p = 0; p < 2; p++) {
#pragma unroll
        for (int j = 0; j < 8; j++) {
            const int c = bx * 128 + tx + 16 * j;
            float vl0, vl1, vh0, vh1;
            UNPACK2_(vl0, vl1, acc2[p][j]);      // low rows, q = 2p, 2p+1
            UNPACK2_(vh0, vh1, acc2[2 + p][j]);  // high rows, same q
#pragma unroll
            for (int q2 = 0; q2 < 2; q2++) {
                const int q = 2 * p + q2;
                const int rL = by * 64 + ty * 4 + q;
                const int rH = Mh + rL;
                const float vlow = q2 ? vl1 : vl0;
                const float vhigh = q2 ? vh1 : vh0;
                if (MODE == 0) {
                    float bias = e0[c];
                    float valL = vlow + bias;
                    float valH = vhigh + bias;
                    if (c >= 512) {
                        valL = 1.0f + 0.05f * tanhf(valL);
                        valH = 1.0f + 0.05f * tanhf(valH);
                    }
                    size_t o0 = (size_t)(c >> 8) * M * 256 + (c & 255);
                    out[o0 + (size_t)rL * 256] = valL;
                    out[o0 + (size_t)rH * 256] = valH;
                } else if (MODE == 3) {
                    out[(size_t)rL * 256 + c] = vlow;
                    out[(size_t)rH * 256 + c] = vhigh;
                } else {
                    size_t iL = (size_t)rL * 256 + c;
                    size_t iH = (size_t)rH * 256 + c;   // == iL + half
                    float u0, u1;
                    tf_uniform2(rk0, rk1, (uint32_t)iL, half, u0, u1);
                    if (MODE == 1) {
                        float wsL = e0[iL], wsH = e0[iH];
                        float pL = sigmoidf_(fmaf(vlow, wsL, e1[iL]));
                        float pH = sigmoidf_(fmaf(vhigh, wsH, e1[iH]));
                        out[iL] = (u0 < pL) ? wsL : 0.0f;
                        out[iH] = (u1 < pH) ? wsH : 0.0f;
                    } else {
                        float pL = sigmoidf_(vlow + e0[iL]);
                        float pH = sigmoidf_(vhigh + e0[iH]);
                        out[iL] = (u0 < pL) ? 1.0f : 0.0f;
                        out[iH] = (u1 < pH) ? 1.0f : 0.0f;
                    }
                }
            }
        }
    }
}

// ---------------- free-energy row reduce (deterministic) ----------------
__global__ void __launch_bounds__(256) fe_reduce_kernel(
    const float* __restrict__ vw, const float* __restrict__ v,
    const float* __restrict__ bmod, const float* __restrict__ cmod,
    const float* __restrict__ ws, const float* __restrict__ Wsum,
    float sign, float* __restrict__ part, int partBase)
{
    __shared__ float sW[256];
    __shared__ float wres[8];
    int t = threadIdx.x;
    sW[t] = Wsum[t];
    __syncthreads();
    int warp = t >> 5, lane = t & 31;
    int r = blockIdx.x * 8 + warp;
    size_t base = (size_t)r * 256;
    float s2v = 0.0f, s2f = 0.0f, s1v = 0.0f, s1f = 0.0f;
#pragma unroll
    for (int jj = 0; jj < 8; jj++) {
        int c = jj * 32 + lane;
        float tt = vw[base + c];
        float w  = ws[base + c];
        float cm = cmod[base + c];
        float tv = tt * w;
        float lv = tv + cm;
        float lf = fmaf(sW[c], w, cm) - tv;
        s2v += softplusf_(lv);
        s2f += softplusf_(lf);
        float bm = bmod[base + c];
        float vv = v[base + c];
        s1v = fmaf(vv, bm, s1v);
        s1f = fmaf(1.0f - vv, bm, s1f);
    }
#pragma unroll
    for (int o = 16; o > 0; o >>= 1) {
        s2v += __shfl_xor_sync(0xffffffffu, s2v, o);
        s2f += __shfl_xor_sync(0xffffffffu, s2f, o);
        s1v += __shfl_xor_sync(0xffffffffu, s1v, o);
        s1f += __shfl_xor_sync(0xffffffffu, s1f, o);
    }
    if (lane == 0) {
        float av = s1v + s2v;
        float af = s1f + s2f;
        float mx = fmaxf(av, af);
        float fe = -(mx + log1pf(expf(-fabsf(av - af))));
        wres[warp] = sign * fe;
    }
    __syncthreads();
    if (t == 0) {
        float s = 0.0f;
#pragma unroll
        for (int w = 0; w < 8; w++) s += wres[w];
        part[partBase + blockIdx.x] = s;
    }
}

__global__ void __launch_bounds__(256) final_reduce_kernel(
    const float* __restrict__ part, int n, float invB, float* __restrict__ out)
{
    __shared__ float s[256];
    float acc = 0.0f;
    for (int i = threadIdx.x; i < n; i += 256) acc += part[i];
    s[threadIdx.x] = acc;
    __syncthreads();
    for (int o = 128; o > 0; o >>= 1) {
        if (threadIdx.x < o) s[threadIdx.x] += s[threadIdx.x + o];
        __syncthreads();
    }
    if (threadIdx.x == 0) out[0] = s[0] * invB;
}

// ---------------- host: JAX key chain ----------------
static inline void host_split2(uint32_t k0, uint32_t k1, uint32_t* ka, uint32_t* kb) {
    uint32_t a0 = 0, b0 = 2; tf2x32(k0, k1, a0, b0);
    uint32_t a1 = 1, b1 = 3; tf2x32(k0, k1, a1, b1);
    ka[0] = a0; ka[1] = a1; kb[0] = b0; kb[1] = b1;
}
static inline void host_split3(uint32_t k0, uint32_t k1,
                               uint32_t* kA, uint32_t* kB, uint32_t* kC) {
    uint32_t a0 = 0, b0 = 3; tf2x32(k0, k1, a0, b0);
    uint32_t a1 = 1, b1 = 4; tf2x32(k0, k1, a1, b1);
    uint32_t a2 = 2, b2 = 5; tf2x32(k0, k1, a2, b2);
    kA[0] = a0; kA[1] = a1;
    kB[0] = a2; kB[1] = b0;
    kC[0] = b1; kC[1] = b2;
}

extern "C" void kernel_launch(void* const* d_in, const int* in_sizes, int n_in,
                              void* d_out, int out_size)
{
    const float* v_data = (const float*)d_in[0];
    const float* cond   = (const float*)d_in[1];
    const float* W      = (const float*)d_in[2];
    const float* b      = (const float*)d_in[3];
    const float* c      = (const float*)d_in[4];
    const float* fc1w   = (const float*)d_in[5];
    const float* fc1b   = (const float*)d_in[6];
    const float* fc2w   = (const float*)d_in[7];
    const float* fc2b   = (const float*)d_in[8];

    int B = in_sizes[0] / 256;
    if (B > BMAX) B = BMAX;
    int n_noise = (int)((double)B * 0.1);

    cudaFuncSetAttribute(sgemm_kernel<0>, cudaFuncAttributeMaxDynamicSharedMemorySize, SGEMM_SMEM);
    cudaFuncSetAttribute(sgemm_kernel<1>, cudaFuncAttributeMaxDynamicSharedMemorySize, SGEMM_SMEM);
    cudaFuncSetAttribute(sgemm_kernel<2>, cudaFuncAttributeMaxDynamicSharedMemorySize, SGEMM_SMEM);
    cudaFuncSetAttribute(sgemm_kernel<3>, cudaFuncAttributeMaxDynamicSharedMemorySize, SGEMM_SMEM);

    float *p_x, *p_cond, *p_v, *p_h, *p_t, *p_WT, *p_P, *p_pb, *p_Wsum, *p_part;
    cudaGetSymbolAddress((void**)&p_x,    g_x);
    cudaGetSymbolAddress((void**)&p_cond, g_cond);
    cudaGetSymbolAddress((void**)&p_v,    g_v);
    cudaGetSymbolAddress((void**)&p_h,    g_h);
    cudaGetSymbolAddress((void**)&p_t,    g_t);
    cudaGetSymbolAddress((void**)&p_WT,   g_WT);
    cudaGetSymbolAddress((void**)&p_P,    g_P);
    cudaGetSymbolAddress((void**)&p_pb,   g_pb);
    cudaGetSymbolAddress((void**)&p_Wsum, g_Wsum);
    cudaGetSymbolAddress((void**)&p_part, g_part);
    float* p_bmod = p_cond;
    float* p_cmod = p_cond + (size_t)B * 256;
    float* p_ws   = p_cond + (size_t)2 * B * 256;

    // JAX key chain: key(42) -> split(2) -> 5x split(3)
    uint32_t rng[2] = {0u, 42u};
    uint32_t kn[2];
    host_split2(rng[0], rng[1], rng, kn);
    uint32_t k1s[5][2], k2s[5][2];
    for (int s = 0; s < 5; s++) {
        uint32_t nk[2];
        host_split3(rng[0], rng[1], nk, k1s[s], k2s[s]);
        rng[0] = nk[0]; rng[1] = nk[1];
    }

    prep_kernel<<<128, 256>>>(W, b, c, fc2w, fc2b, p_WT, p_P, p_pb, p_Wsum);
    cond_fc1_kernel<<<B / 64, 256>>>(cond, fc1w, fc1b, p_x);

    dim3 g0(6, B / 128);
    sgemm_kernel<0><<<g0, 256, SGEMM_SMEM>>>(p_x, p_P, p_cond, p_pb, nullptr,
                                             B, 768, 64, 0u, 0u, 0u);

    init_v_kernel<<<2048, 256>>>(v_data, p_v, B, n_noise, kn[0], kn[1]);

    uint32_t half = (uint32_t)B * 128u;
    dim3 g1(2, B / 128);
    for (int s = 0; s < 5; s++) {
        sgemm_kernel<1><<<g1, 256, SGEMM_SMEM>>>(p_v, W, p_h, p_ws, p_cmod,
                                                 B, 256, 256, k1s[s][0], k1s[s][1], half);
        sgemm_kernel<2><<<g1, 256, SGEMM_SMEM>>>(p_h, p_WT, p_v, p_bmod, nullptr,
                                                 B, 256, 256, k2s[s][0], k2s[s][1], half);
    }

    // free energy: data (+) and model (-)
    sgemm_kernel<3><<<g1, 256, SGEMM_SMEM>>>(v_data, W, p_t, nullptr, nullptr,
                                             B, 256, 256, 0u, 0u, 0u);
    fe_reduce_kernel<<<B / 8, 256>>>(p_t, v_data, p_bmod, p_cmod, p_ws, p_Wsum,
                                     1.0f, p_part, 0);
    sgemm_kernel<3><<<g1, 256, SGEMM_SMEM>>>(p_v, W, p_t, nullptr, nullptr,
                                             B, 256, 256, 0u, 0u, 0u);
    fe_reduce_kernel<<<B / 8, 256>>>(p_t, p_v, p_bmod, p_cmod, p_ws, p_Wsum,
                                     -1.0f, p_part, B / 8);

    final_reduce_kernel<<<1, 256>>>(p_part, 2 * (B / 8), 1.0f / (float)B, (float*)d_out);
}

// round 11
// speedup vs baseline: 1.8280x; 1.8280x over previous
#include <cuda_runtime.h>
#include <cuda_bf16.h>
#include <cstdint>
#include <cstddef>

#define BMAX 32768

__device__ float g_x[BMAX * 64];
__device__ float g_cond[3 * BMAX * 256];
__device__ float g_t[BMAX * 256];
__device__ float g_P[64 * 768];
__device__ float g_pb[768];
__device__ float g_Wsum[256];
__device__ float g_part[BMAX / 4];
__device__ __nv_bfloat16 g_v16[BMAX * 256];
__device__ __nv_bfloat16 g_vd16[BMAX * 256];
__device__ __nv_bfloat16 g_ahi[BMAX * 256];
__device__ __nv_bfloat16 g_alo[BMAX * 256];
__device__ __nv_bfloat16 g_alo2[BMAX * 256];
__device__ __nv_bfloat16 g_S1[3][256 * 256];   // v@W:   S1[n*256+k] = split(W[k,n])
__device__ __nv_bfloat16 g_S2[3][256 * 256];   // a@W^T: S2[n*256+k] = split(W[n,k])

__host__ __device__ inline uint32_t rotl32(uint32_t v, int d) { return (v << d) | (v >> (32 - d)); }

__host__ __device__ inline void tf2x32(uint32_t k0, uint32_t k1, uint32_t& x0, uint32_t& x1) {
    uint32_t ks2 = k0 ^ k1 ^ 0x1BD11BDAu;
    x0 += k0; x1 += k1;
    x0 += x1; x1 = rotl32(x1, 13); x1 ^= x0;
    x0 += x1; x1 = rotl32(x1, 15); x1 ^= x0;
    x0 += x1; x1 = rotl32(x1, 26); x1 ^= x0;
    x0 += x1; x1 = rotl32(x1,  6); x1 ^= x0;
    x0 += k1;  x1 += ks2 + 1u;
    x0 += x1; x1 = rotl32(x1, 17); x1 ^= x0;
    x0 += x1; x1 = rotl32(x1, 29); x1 ^= x0;
    x0 += x1; x1 = rotl32(x1, 16); x1 ^= x0;
    x0 += x1; x1 = rotl32(x1, 24); x1 ^= x0;
    x0 += ks2; x1 += k0 + 2u;
    x0 += x1; x1 = rotl32(x1, 13); x1 ^= x0;
    x0 += x1; x1 = rotl32(x1, 15); x1 ^= x0;
    x0 += x1; x1 = rotl32(x1, 26); x1 ^= x0;
    x0 += x1; x1 = rotl32(x1,  6); x1 ^= x0;
    x0 += k0;  x1 += k1 + 3u;
    x0 += x1; x1 = rotl32(x1, 17); x1 ^= x0;
    x0 += x1; x1 = rotl32(x1, 29); x1 ^= x0;
    x0 += x1; x1 = rotl32(x1, 16); x1 ^= x0;
    x0 += x1; x1 = rotl32(x1, 24); x1 ^= x0;
    x0 += k1;  x1 += ks2 + 4u;
    x0 += x1; x1 = rotl32(x1, 13); x1 ^= x0;
    x0 += x1; x1 = rotl32(x1, 15); x1 ^= x0;
    x0 += x1; x1 = rotl32(x1, 26); x1 ^= x0;
    x0 += x1; x1 = rotl32(x1,  6); x1 ^= x0;
    x0 += ks2; x1 += k0 + 5u;
}

__device__ inline float tf_uniform(uint32_t k0, uint32_t k1, uint32_t f, uint32_t half) {
    uint32_t sec = (f >= half) ? 1u : 0u;
    uint32_t lane = sec ? (f - half) : f;
    uint32_t x0 = lane, x1 = lane + half;
    tf2x32(k0, k1, x0, x1);
    uint32_t bits = sec ? x1 : x0;
    return __uint_as_float((bits >> 9) | 0x3f800000u) - 1.0f;
}

__device__ inline void tf_uniform2(uint32_t k0, uint32_t k1, uint32_t f, uint32_t half,
                                   float& u0, float& u1) {
    uint32_t x0 = f, x1 = f + half;
    tf2x32(k0, k1, x0, x1);
    u0 = __uint_as_float((x0 >> 9) | 0x3f800000u) - 1.0f;
    u1 = __uint_as_float((x1 >> 9) | 0x3f800000u) - 1.0f;
}

__device__ inline float sigmoidf_(float x) {
    float e = expf(-fabsf(x));
    float s = 1.0f / (1.0f + e);
    return (x >= 0.0f) ? s : (1.0f - s);
}
__device__ inline float softplusf_(float x) {
    return fmaxf(x, 0.0f) + log1pf(expf(-fabsf(x)));
}

// ---------------- smem / mma helpers (sm_80 baseline instructions only) ----------------
__device__ __forceinline__ uint32_t smem_u32(const void* p) {
    uint32_t a;
    asm("{ .reg .u64 t; cvta.to.shared.u64 t, %1; cvt.u32.u64 %0, t; }" : "=r"(a) : "l"(p));
    return a;
}
#define SWZ(o) ((o) ^ (((o) >> 3) & 0x70))

#define CP16(dst, src) \
    asm volatile("cp.async.cg.shared.global [%0], [%1], 16;" :: "r"(dst), "l"(src))
#define CPC() asm volatile("cp.async.commit_group;" ::: "memory")
template <int N> __device__ __forceinline__ void cp_wait() {
    asm volatile("cp.async.wait_group %0;" :: "n"(N) : "memory");
}

__device__ __forceinline__ void ldm4(uint32_t* r, uint32_t a) {
    asm volatile("ldmatrix.sync.aligned.m8n8.x4.shared.b16 {%0,%1,%2,%3}, [%4];"
        : "=r"(r[0]), "=r"(r[1]), "=r"(r[2]), "=r"(r[3]) : "r"(a));
}
__device__ __forceinline__ void mma16816(float* d, const uint32_t* a, const uint32_t* b) {
    asm volatile(
        "mma.sync.aligned.m16n8k16.row.col.f32.bf16.bf16.f32 "
        "{%0,%1,%2,%3}, {%4,%5,%6,%7}, {%8,%9}, {%0,%1,%2,%3};"
        : "+f"(d[0]), "+f"(d[1]), "+f"(d[2]), "+f"(d[3])
        : "r"(a[0]), "r"(a[1]), "r"(a[2]), "r"(a[3]), "r"(b[0]), "r"(b[1]));
}

__device__ __forceinline__ uint32_t pk(float x, float y) {
    __nv_bfloat162 h = __floats2bfloat162_rn(x, y);
    return *(uint32_t*)&h;
}
__device__ __forceinline__ void split3(float a, float& h, float& l, float& m) {
    h = __bfloat162float(__float2bfloat16(a));
    float r = a - h;
    l = __bfloat162float(__float2bfloat16(r));
    m = r - l;
}

// ---------------- prep: splits + combined cond-param weights + Wsum ----------------
__global__ void __launch_bounds__(256) prep_kernel(
    const float* __restrict__ W, const float* __restrict__ b, const float* __restrict__ c,
    const float* __restrict__ fc2w, const float* __restrict__ fc2b)
{
    int idx = blockIdx.x * blockDim.x + threadIdx.x;
    int stride = gridDim.x * blockDim.x;
    for (int i = idx; i < 256 * 256; i += stride) {
        int n = i >> 8, k = i & 255;
        float w1 = W[k * 256 + n];
        float h1, l1, m1; split3(w1, h1, l1, m1);
        g_S1[0][i] = __float2bfloat16(h1);
        g_S1[1][i] = __float2bfloat16(l1);
        g_S1[2][i] = __float2bfloat16(m1);
        float w2 = W[n * 256 + k];
        float h2, l2, m2; split3(w2, h2, l2, m2);
        g_S2[0][i] = __float2bfloat16(h2);
        g_S2[1][i] = __float2bfloat16(l2);
        g_S2[2][i] = __float2bfloat16(m2);
    }
    for (int i = idx; i < 64 * 768; i += stride) {
        int k = i / 768, n = i % 768;
        float val;
        if (n < 256)      val = b[n] * fc2w[n * 64 + k] + fc2w[(256 + n) * 64 + k];
        else if (n < 512) { int j = n - 256; val = c[j] * fc2w[(512 + j) * 64 + k] + fc2w[(768 + j) * 64 + k]; }
        else              { int j = n - 512; val = fc2w[(1024 + j) * 64 + k]; }
        g_P[k * 768 + n] = val;
    }
    for (int i = idx; i < 768; i += stride) {
        float val;
        if (i < 256)      val = b[i] * (1.0f + fc2b[i]) + fc2b[256 + i];
        else if (i < 512) { int j = i - 256; val = c[j] * (1.0f + fc2b[512 + j]) + fc2b[768 + j]; }
        else              { int j = i - 512; val = fc2b[1024 + j]; }
        g_pb[i] = val;
    }
    for (int i = idx; i < 256; i += stride) {
        float s = 0.0f;
        for (int rr = 0; rr < 256; rr++) s += W[rr * 256 + i];
        g_Wsum[i] = s;
    }
}

// ---------------- cond fc1: x = tanh(cond @ fc1_w.T + fc1_b) ----------------
__global__ void __launch_bounds__(256) cond_fc1_kernel(
    const float* __restrict__ cond, const float* __restrict__ fc1w,
    const float* __restrict__ fc1b, float* __restrict__ xout)
{
    __shared__ float Cs[64][65];
    __shared__ float Ws[64][65];
    int t = threadIdx.x;
    int r0 = blockIdx.x * 64;
#pragma unroll
    for (int l = 0; l < 4; l++) {
        int id = t + l * 256;
        int j = id >> 4, k4 = (id & 15) << 2;
        float4 w = *(const float4*)(fc1w + j * 64 + k4);
        Ws[k4 + 0][j] = w.x; Ws[k4 + 1][j] = w.y; Ws[k4 + 2][j] = w.z; Ws[k4 + 3][j] = w.w;
    }
#pragma unroll
    for (int l = 0; l < 4; l++) {
        int id = t + l * 256;
        int i = id >> 4, k4 = (id & 15) << 2;
        float4 v = *(const float4*)(cond + (size_t)(r0 + i) * 64 + k4);
        Cs[i][k4 + 0] = v.x; Cs[i][k4 + 1] = v.y; Cs[i][k4 + 2] = v.z; Cs[i][k4 + 3] = v.w;
    }
    __syncthreads();
    int tx = t & 15, ty = t >> 4;
    float acc[4][4];
#pragma unroll
    for (int i = 0; i < 4; i++)
#pragma unroll
        for (int j = 0; j < 4; j++) acc[i][j] = 0.0f;
#pragma unroll 8
    for (int k = 0; k < 64; k++) {
        float a[4], bv[4];
#pragma unroll
        for (int i = 0; i < 4; i++) a[i] = Cs[ty * 4 + i][k];
#pragma unroll
        for (int j = 0; j < 4; j++) bv[j] = Ws[k][tx * 4 + j];
#pragma unroll
        for (int i = 0; i < 4; i++)
#pragma unroll
            for (int j = 0; j < 4; j++) acc[i][j] = fmaf(a[i], bv[j], acc[i][j]);
    }
#pragma unroll
    for (int i = 0; i < 4; i++) {
        int r = r0 + ty * 4 + i;
#pragma unroll
        for (int j = 0; j < 4; j++) {
            int jj = tx * 4 + j;
            xout[(size_t)r * 64 + jj] = tanhf(acc[i][j] + fc1b[jj]);
        }
    }
}

// ---------------- cond-param SGEMM (fp32, K=64, N=768) ----------------
__global__ void __launch_bounds__(256, 2) sgemm0_kernel(
    const float* __restrict__ A, const float* __restrict__ Bm,
    float* __restrict__ out, const float* __restrict__ pb, int M)
{
    __shared__ float As[16][132];
    __shared__ float Bs[16][128];
    const int t = threadIdx.x;
    const int tx = t & 15, ty = t >> 4;
    const int bx = blockIdx.x, by = blockIdx.y;
    const int N = 768, K = 64;
    const float* Ab = A + (size_t)by * 128 * K;
    const float* Bb = Bm + (size_t)bx * 128;
    float acc[8][8];
#pragma unroll
    for (int i = 0; i < 8; i++)
#pragma unroll
        for (int j = 0; j < 8; j++) acc[i][j] = 0.0f;
    for (int kb = 0; kb < K; kb += 16) {
#pragma unroll
        for (int l = 0; l < 2; l++) {
            int id = t + l * 256;
            int row = id >> 2, c4 = (id & 3) << 2;
            float4 va = *(const float4*)(Ab + (size_t)row * K + kb + c4);
            As[c4 + 0][row] = va.x; As[c4 + 1][row] = va.y;
            As[c4 + 2][row] = va.z; As[c4 + 3][row] = va.w;
        }
#pragma unroll
        for (int l = 0; l < 2; l++) {
            int id = t + l * 256;
            int kk = id >> 5, n4 = (id & 31) << 2;
            *(float4*)&Bs[kk][n4] = *(const float4*)(Bb + (size_t)(kb + kk) * N + n4);
        }
        __syncthreads();
#pragma unroll
        for (int kk = 0; kk < 16; kk++) {
            float a[8], bv[8];
#pragma unroll
            for (int i = 0; i < 8; i++) a[i] = As[kk][ty * 8 + i];
#pragma unroll
            for (int j = 0; j < 8; j++) bv[j] = Bs[kk][tx * 8 + j];
#pragma unroll
            for (int i = 0; i < 8; i++)
#pragma unroll
                for (int j = 0; j < 8; j++) acc[i][j] = fmaf(a[i], bv[j], acc[i][j]);
        }
        __syncthreads();
    }
#pragma unroll
    for (int i = 0; i < 8; i++) {
        int r = by * 128 + ty * 8 + i;
#pragma unroll
        for (int j = 0; j < 8; j++) {
            int c = bx * 128 + tx * 8 + j;
            float val = acc[i][j] + pb[c];
            if (c >= 512) val = 1.0f + 0.05f * tanhf(val);
            out[(size_t)(c >> 8) * M * 256 + (size_t)r * 256 + (c & 255)] = val;
        }
    }
}

// ---------------- init: vd16 = bf16(v_data); v16 = noise/copy ----------------
__global__ void __launch_bounds__(256) init_v_kernel(
    const float* __restrict__ vdata, __nv_bfloat16* __restrict__ v16,
    __nv_bfloat16* __restrict__ vd16, int B, int n_noise, uint32_t k0, uint32_t k1)
{
    int total = B * 256;
    uint32_t half = (uint32_t)(n_noise * 128);
    for (int idx = blockIdx.x * blockDim.x + threadIdx.x; idx < total;
         idx += gridDim.x * blockDim.x) {
        int r = idx >> 8;
        float vd = vdata[idx];
        vd16[idx] = __float2bfloat16(vd);
        float val = vd;
        if (r < n_noise) {
            float u = tf_uniform(k0, k1, (uint32_t)idx, half);
            val = (u < 0.5f) ? 1.0f : 0.0f;
        }
        v16[idx] = __float2bfloat16(val);
    }
}

// ---------------- bf16 mma.sync GEMM (M=128 split rows, N=128 per CTA) ----------------
// MODE 1: h-sample -> ahi/alo/alo2 (splits of h?ws:0). A=v16, B=S1, 3 streams.
// MODE 2: v-sample -> v16.  A=ahi/alo/alo2, B=S2, 6 streams.
// MODE 3: plain fp32 store -> outf. A binary, B=S1, 3 streams.
#define MG_SMEM 65536

template <int MODE>
__global__ void __launch_bounds__(256, 2) mma_gemm(
    const __nv_bfloat16* __restrict__ A0, const __nv_bfloat16* __restrict__ A1,
    const __nv_bfloat16* __restrict__ A2,
    const __nv_bfloat16* __restrict__ B0, const __nv_bfloat16* __restrict__ B1,
    const __nv_bfloat16* __restrict__ B2,
    const float* __restrict__ e0, const float* __restrict__ e1,
    float* __restrict__ outf,
    __nv_bfloat16* __restrict__ o0, __nv_bfloat16* __restrict__ o1,
    __nv_bfloat16* __restrict__ o2,
    int Bn, uint32_t rk0, uint32_t rk1, uint32_t hlf)
{
    extern __shared__ char sm[];
    const uint32_t smb = smem_u32(sm);
    const int t = threadIdx.x;
    const int lane = t & 31;
    const int wid = t >> 5;
    const int wm = wid & 1, wn = wid >> 1;
    const int bx = blockIdx.x, by = blockIdx.y;
    const int Mh = Bn >> 1;
    constexpr int NS = (MODE == 2) ? 6 : 3;
    constexpr int NIT = NS * 4;

    const int SA2[6] = {0, 0, 0, 1, 1, 2};
    const int SB2[6] = {0, 1, 2, 0, 1, 0};
    const int SA1[6] = {0, 0, 0, 0, 0, 0};
    const int SB1[6] = {0, 1, 2, 0, 0, 0};
    const int* SA = (MODE == 2) ? SA2 : SA1;
    const int* SB = (MODE == 2) ? SB2 : SB1;

    // per-thread cp.async lanes: 4 A units + 4 B units of 16B per iteration
    size_t asrc[4], bsrc[4];
    uint32_t sdst[4];
#pragma unroll
    for (int i = 0; i < 4; i++) {
        int u = t + i * 256;
        int r = u >> 3, q = u & 7;
        int gr = (r < 64) ? (by * 64 + r) : (Mh + by * 64 + (r - 64));
        asrc[i] = (size_t)gr * 256 + q * 8;
        bsrc[i] = (size_t)(bx * 128 + r) * 256 + q * 8;
        sdst[i] = (uint32_t)SWZ(r * 128 + q * 16);
    }

    float acc[4][4][4];
#pragma unroll
    for (int j = 0; j < 4; j++)
#pragma unroll
        for (int n = 0; n < 4; n++)
#pragma unroll
            for (int q = 0; q < 4; q++) acc[j][n][q] = 0.0f;

    auto stage = [&](int it) {
        int s = it >> 2, kc = (it & 3) * 64, buf = it & 1;
        int sa = SA[s], sb = SB[s];
        const __nv_bfloat16* Asrc = (sa == 0) ? A0 : ((sa == 1) ? A1 : A2);
        const __nv_bfloat16* Bsrc = (sb == 0) ? B0 : ((sb == 1) ? B1 : B2);
        uint32_t smA = smb + buf * 16384;
        uint32_t smB = smb + 32768 + buf * 16384;
#pragma unroll
        for (int i = 0; i < 4; i++) {
            CP16(smA + sdst[i], Asrc + asrc[i] + kc);
            CP16(smB + sdst[i], Bsrc + bsrc[i] + kc);
        }
        CPC();
    };

    // ldmatrix lane address components
    const int arow = lane & 15;
    const int acolb = (lane >> 4) * 16;
    const int brow = (lane & 7) + (lane >> 4) * 8;
    const int bcolb = ((lane >> 3) & 1) * 16;

    stage(0);
    for (int it = 0; it < NIT; it++) {
        if (it + 1 < NIT) { stage(it + 1); cp_wait<1>(); }
        else              { cp_wait<0>(); }
        __syncthreads();
        const int buf = it & 1;
        const uint32_t smA = smb + buf * 16384;
        const uint32_t smB = smb + 32768 + buf * 16384;
#pragma unroll
        for (int kk = 0; kk < 4; kk++) {
            uint32_t a[4][4];
#pragma unroll
            for (int j = 0; j < 4; j++)
                ldm4(a[j], smA + SWZ((wm * 16 + j * 32 + arow) * 128 + kk * 32 + acolb));
            uint32_t bf[4][2];
#pragma unroll
            for (int nb = 0; nb < 2; nb++) {
                uint32_t r4[4];
                ldm4(r4, smB + SWZ((wn * 32 + nb * 16 + brow) * 128 + kk * 32 + bcolb));
                bf[nb * 2][0] = r4[0]; bf[nb * 2][1] = r4[1];
                bf[nb * 2 + 1][0] = r4[2]; bf[nb * 2 + 1][1] = r4[3];
            }
#pragma unroll
            for (int j = 0; j < 4; j++)
#pragma unroll
                for (int n = 0; n < 4; n++)
                    mma16816(acc[j][n], a[j], bf[n]);
        }
        __syncthreads();
    }

    // epilogue: tiles (j, j+2) pair rows (r, r+64) -> (gL, B/2+gL) for threefry pairing
    const int g = lane >> 2, t4 = lane & 3;
    const uint32_t cbase = (uint32_t)(bx * 128 + wn * 32 + t4 * 2);
#pragma unroll
    for (int j = 0; j < 2; j++)
#pragma unroll
    for (int hf = 0; hf < 2; hf++) {
        int tr = wm * 16 + j * 32 + g + hf * 8;          // 0..63
        uint32_t rowL = (uint32_t)(by * 64 + tr) * 256u;
#pragma unroll
        for (int n = 0; n < 4; n++) {
            uint32_t iL = rowL + cbase + n * 8;
            uint32_t iH = iL + hlf;
            float vL0 = acc[j][n][hf * 2 + 0], vL1 = acc[j][n][hf * 2 + 1];
            float vH0 = acc[j + 2][n][hf * 2 + 0], vH1 = acc[j + 2][n][hf * 2 + 1];
            if (MODE == 3) {
                *(float2*)(outf + iL) = make_float2(vL0, vL1);
                *(float2*)(outf + iH) = make_float2(vH0, vH1);
            } else {
                float u0, u1, u2, u3;
                tf_uniform2(rk0, rk1, iL, hlf, u0, u1);
                tf_uniform2(rk0, rk1, iL + 1, hlf, u2, u3);
                if (MODE == 1) {
                    float2 wsL = *(const float2*)(e0 + iL), wsH = *(const float2*)(e0 + iH);
                    float2 cmL = *(const float2*)(e1 + iL), cmH = *(const float2*)(e1 + iH);
                    float a00 = (u0 < sigmoidf_(fmaf(vL0, wsL.x, cmL.x))) ? wsL.x : 0.0f;
                    float a01 = (u2 < sigmoidf_(fmaf(vL1, wsL.y, cmL.y))) ? wsL.y : 0.0f;
                    float a10 = (u1 < sigmoidf_(fmaf(vH0, wsH.x, cmH.x))) ? wsH.x : 0.0f;
                    float a11 = (u3 < sigmoidf_(fmaf(vH1, wsH.y, cmH.y))) ? wsH.y : 0.0f;
                    float h0, l0, m0, h1, l1, m1, h2, l2, m2, h3, l3, m3;
                    split3(a00, h0, l0, m0); split3(a01, h1, l1, m1);
                    split3(a10, h2, l2, m2); split3(a11, h3, l3, m3);
                    *(uint32_t*)(o0 + iL) = pk(h0, h1); *(uint32_t*)(o0 + iH) = pk(h2, h3);
                    *(uint32_t*)(o1 + iL) = pk(l0, l1); *(uint32_t*)(o1 + iH) = pk(l2, l3);
                    *(uint32_t*)(o2 + iL) = pk(m0, m1); *(uint32_t*)(o2 + iH) = pk(m2, m3);
                } else {
                    float2 bmL = *(const float2*)(e0 + iL), bmH = *(const float2*)(e0 + iH);
                    float b00 = (u0 < sigmoidf_(vL0 + bmL.x)) ? 1.0f : 0.0f;
                    float b01 = (u2 < sigmoidf_(vL1 + bmL.y)) ? 1.0f : 0.0f;
                    float b10 = (u1 < sigmoidf_(vH0 + bmH.x)) ? 1.0f : 0.0f;
                    float b11 = (u3 < sigmoidf_(vH1 + bmH.y)) ? 1.0f : 0.0f;
                    *(uint32_t*)(o0 + iL) = pk(b00, b01);
                    *(uint32_t*)(o0 + iH) = pk(b10, b11);
                }
            }
        }
    }
}

// ---------------- free-energy reduce ----------------
template <int VB>
__global__ void __launch_bounds__(256) fe_reduce_kernel(
    const float* __restrict__ vw, const float* __restrict__ vf,
    const __nv_bfloat16* __restrict__ vb,
    const float* __restrict__ bmod, const float* __restrict__ cmod,
    const float* __restrict__ ws, const float* __restrict__ Wsum,
    float sign, float* __restrict__ part, int partBase)
{
    __shared__ float sW[256];
    __shared__ float wres[8];
    int t = threadIdx.x;
    sW[t] = Wsum[t];
    __syncthreads();
    int warp = t >> 5, lane = t & 31;
    int r = blockIdx.x * 8 + warp;
    size_t base = (size_t)r * 256;
    float s2v = 0.0f, s2f = 0.0f, s1v = 0.0f, s1f = 0.0f;
#pragma unroll
    for (int jj = 0; jj < 8; jj++) {
        int c = jj * 32 + lane;
        float tt = vw[base + c];
        float w  = ws[base + c];
        float cm = cmod[base + c];
        float tv = tt * w;
        s2v += softplusf_(tv + cm);
        s2f += softplusf_(fmaf(sW[c], w, cm) - tv);
        float bm = bmod[base + c];
        float vv = VB ? __bfloat162float(vb[base + c]) : vf[base + c];
        s1v = fmaf(vv, bm, s1v);
        s1f = fmaf(1.0f - vv, bm, s1f);
    }
#pragma unroll
    for (int o = 16; o > 0; o >>= 1) {
        s2v += __shfl_xor_sync(0xffffffffu, s2v, o);
        s2f += __shfl_xor_sync(0xffffffffu, s2f, o);
        s1v += __shfl_xor_sync(0xffffffffu, s1v, o);
        s1f += __shfl_xor_sync(0xffffffffu, s1f, o);
    }
    if (lane == 0) {
        float av = s1v + s2v;
        float af = s1f + s2f;
        float mx = fmaxf(av, af);
        wres[warp] = sign * (-(mx + log1pf(expf(-fabsf(av - af)))));
    }
    __syncthreads();
    if (t == 0) {
        float s = 0.0f;
#pragma unroll
        for (int w = 0; w < 8; w++) s += wres[w];
        part[partBase + blockIdx.x] = s;
    }
}

__global__ void __launch_bounds__(256) final_reduce_kernel(
    const float* __restrict__ part, int n, float invB, float* __restrict__ out)
{
    __shared__ float s[256];
    float acc = 0.0f;
    for (int i = threadIdx.x; i < n; i += 256) acc += part[i];
    s[threadIdx.x] = acc;
    __syncthreads();
    for (int o = 128; o > 0; o >>= 1) {
        if (threadIdx.x < o) s[threadIdx.x] += s[threadIdx.x + o];
        __syncthreads();
    }
    if (threadIdx.x == 0) out[0] = s[0] * invB;
}

// ---------------- host: JAX key chain ----------------
static inline void host_split2(uint32_t k0, uint32_t k1, uint32_t* ka, uint32_t* kb) {
    uint32_t a0 = 0, b0 = 2; tf2x32(k0, k1, a0, b0);
    uint32_t a1 = 1, b1 = 3; tf2x32(k0, k1, a1, b1);
    ka[0] = a0; ka[1] = a1; kb[0] = b0; kb[1] = b1;
}
static inline void host_split3(uint32_t k0, uint32_t k1,
                               uint32_t* kA, uint32_t* kB, uint32_t* kC) {
    uint32_t a0 = 0, b0 = 3; tf2x32(k0, k1, a0, b0);
    uint32_t a1 = 1, b1 = 4; tf2x32(k0, k1, a1, b1);
    uint32_t a2 = 2, b2 = 5; tf2x32(k0, k1, a2, b2);
    kA[0] = a0; kA[1] = a1;
    kB[0] = a2; kB[1] = b0;
    kC[0] = b1; kC[1] = b2;
}

extern "C" void kernel_launch(void* const* d_in, const int* in_sizes, int n_in,
                              void* d_out, int out_size)
{
    const float* v_data = (const float*)d_in[0];
    const float* cond   = (const float*)d_in[1];
    const float* W      = (const float*)d_in[2];
    const float* b      = (const float*)d_in[3];
    const float* c      = (const float*)d_in[4];
    const float* fc1w   = (const float*)d_in[5];
    const float* fc1b   = (const float*)d_in[6];
    const float* fc2w   = (const float*)d_in[7];
    const float* fc2b   = (const float*)d_in[8];

    int B = in_sizes[0] / 256;
    if (B > BMAX) B = BMAX;
    int n_noise = (int)((double)B * 0.1);

    cudaFuncSetAttribute(mma_gemm<1>, cudaFuncAttributeMaxDynamicSharedMemorySize, MG_SMEM);
    cudaFuncSetAttribute(mma_gemm<2>, cudaFuncAttributeMaxDynamicSharedMemorySize, MG_SMEM);
    cudaFuncSetAttribute(mma_gemm<3>, cudaFuncAttributeMaxDynamicSharedMemorySize, MG_SMEM);

    float *p_x, *p_cond, *p_t, *p_Wsum, *p_part, *p_P, *p_pb;
    __nv_bfloat16 *p_v16, *p_vd16, *p_ahi, *p_alo, *p_alo2, *p_S1, *p_S2;
    cudaGetSymbolAddress((void**)&p_x,    g_x);
    cudaGetSymbolAddress((void**)&p_cond, g_cond);
    cudaGetSymbolAddress((void**)&p_t,    g_t);
    cudaGetSymbolAddress((void**)&p_Wsum, g_Wsum);
    cudaGetSymbolAddress((void**)&p_part, g_part);
    cudaGetSymbolAddress((void**)&p_P,    g_P);
    cudaGetSymbolAddress((void**)&p_pb,   g_pb);
    cudaGetSymbolAddress((void**)&p_v16,  g_v16);
    cudaGetSymbolAddress((void**)&p_vd16, g_vd16);
    cudaGetSymbolAddress((void**)&p_ahi,  g_ahi);
    cudaGetSymbolAddress((void**)&p_alo,  g_alo);
    cudaGetSymbolAddress((void**)&p_alo2, g_alo2);
    cudaGetSymbolAddress((void**)&p_S1,   g_S1);
    cudaGetSymbolAddress((void**)&p_S2,   g_S2);
    float* p_bmod = p_cond;
    float* p_cmod = p_cond + (size_t)B * 256;
    float* p_ws   = p_cond + (size_t)2 * B * 256;
    __nv_bfloat16* S1a = p_S1; __nv_bfloat16* S1b = p_S1 + 65536; __nv_bfloat16* S1c = p_S1 + 131072;
    __nv_bfloat16* S2a = p_S2; __nv_bfloat16* S2b = p_S2 + 65536; __nv_bfloat16* S2c = p_S2 + 131072;

    uint32_t rng[2] = {0u, 42u};
    uint32_t kn[2];
    host_split2(rng[0], rng[1], rng, kn);
    uint32_t k1s[5][2], k2s[5][2];
    for (int s = 0; s < 5; s++) {
        uint32_t nk[2];
        host_split3(rng[0], rng[1], nk, k1s[s], k2s[s]);
        rng[0] = nk[0]; rng[1] = nk[1];
    }

    prep_kernel<<<128, 256>>>(W, b, c, fc2w, fc2b);
    cond_fc1_kernel<<<B / 64, 256>>>(cond, fc1w, fc1b, p_x);
    dim3 g0(6, B / 128);
    sgemm0_kernel<<<g0, 256>>>(p_x, p_P, p_cond, p_pb, B);
    init_v_kernel<<<2048, 256>>>(v_data, p_v16, p_vd16, B, n_noise, kn[0], kn[1]);

    uint32_t hlf = (uint32_t)B * 128u;
    dim3 gmm(2, B / 128);
    for (int s = 0; s < 5; s++) {
        mma_gemm<1><<<gmm, 256, MG_SMEM>>>(p_v16, nullptr, nullptr,
                                           S1a, S1b, S1c,
                                           p_ws, p_cmod, nullptr,
                                           p_ahi, p_alo, p_alo2,
                                           B, k1s[s][0], k1s[s][1], hlf);
        mma_gemm<2><<<gmm, 256, MG_SMEM>>>(p_ahi, p_alo, p_alo2,
                                           S2a, S2b, S2c,
                                           p_bmod, nullptr, nullptr,
                                           p_v16, nullptr, nullptr,
                                           B, k2s[s][0], k2s[s][1], hlf);
    }

    mma_gemm<3><<<gmm, 256, MG_SMEM>>>(p_vd16, nullptr, nullptr,
                                       S1a, S1b, S1c,
                                       nullptr, nullptr, p_t,
                                       nullptr, nullptr, nullptr,
                                       B, 0u, 0u, hlf);
    fe_reduce_kernel<0><<<B / 8, 256>>>(p_t, v_data, nullptr, p_bmod, p_cmod, p_ws,
                                        p_Wsum, 1.0f, p_part, 0);
    mma_gemm<3><<<gmm, 256, MG_SMEM>>>(p_v16, nullptr, nullptr,
                                       S1a, S1b, S1c,
                                       nullptr, nullptr, p_t,
                                       nullptr, nullptr, nullptr,
                                       B, 0u, 0u, hlf);
    fe_reduce_kernel<1><<<B / 8, 256>>>(p_t, nullptr, p_v16, p_bmod, p_cmod, p_ws,
                                        p_Wsum, -1.0f, p_part, B / 8);

    final_reduce_kernel<<<1, 256>>>(p_part, 2 * (B / 8), 1.0f / (float)B, (float*)d_out);
}

// round 12
// speedup vs baseline: 2.4737x; 1.3533x over previous
#include <cuda_runtime.h>
#include <cuda_fp16.h>
#include <cstdint>
#include <cstddef>

#define BMAX 32768

__device__ float g_x[BMAX * 64];
__device__ float g_cond[3 * BMAX * 256];
__device__ float g_t[BMAX * 256];
__device__ float g_P[64 * 768];
__device__ float g_pb[768];
__device__ float g_Wsum[256];
__device__ float g_part[BMAX / 4];
__device__ __half g_v16[BMAX * 256];
__device__ __half g_vd16[BMAX * 256];
__device__ __half g_ahi[BMAX * 256];
__device__ __half g_alo[BMAX * 256];
__device__ __half g_S1[2][256 * 256];   // v@W:   S1[s][n*256+k] = split_s(W[k,n])
__device__ __half g_S2[2][256 * 256];   // a@W^T: S2[s][n*256+k] = split_s(W[n,k])

__host__ __device__ inline uint32_t rotl32(uint32_t v, int d) { return (v << d) | (v >> (32 - d)); }

__host__ __device__ inline void tf2x32(uint32_t k0, uint32_t k1, uint32_t& x0, uint32_t& x1) {
    uint32_t ks2 = k0 ^ k1 ^ 0x1BD11BDAu;
    x0 += k0; x1 += k1;
    x0 += x1; x1 = rotl32(x1, 13); x1 ^= x0;
    x0 += x1; x1 = rotl32(x1, 15); x1 ^= x0;
    x0 += x1; x1 = rotl32(x1, 26); x1 ^= x0;
    x0 += x1; x1 = rotl32(x1,  6); x1 ^= x0;
    x0 += k1;  x1 += ks2 + 1u;
    x0 += x1; x1 = rotl32(x1, 17); x1 ^= x0;
    x0 += x1; x1 = rotl32(x1, 29); x1 ^= x0;
    x0 += x1; x1 = rotl32(x1, 16); x1 ^= x0;
    x0 += x1; x1 = rotl32(x1, 24); x1 ^= x0;
    x0 += ks2; x1 += k0 + 2u;
    x0 += x1; x1 = rotl32(x1, 13); x1 ^= x0;
    x0 += x1; x1 = rotl32(x1, 15); x1 ^= x0;
    x0 += x1; x1 = rotl32(x1, 26); x1 ^= x0;
    x0 += x1; x1 = rotl32(x1,  6); x1 ^= x0;
    x0 += k0;  x1 += k1 + 3u;
    x0 += x1; x1 = rotl32(x1, 17); x1 ^= x0;
    x0 += x1; x1 = rotl32(x1, 29); x1 ^= x0;
    x0 += x1; x1 = rotl32(x1, 16); x1 ^= x0;
    x0 += x1; x1 = rotl32(x1, 24); x1 ^= x0;
    x0 += k1;  x1 += ks2 + 4u;
    x0 += x1; x1 = rotl32(x1, 13); x1 ^= x0;
    x0 += x1; x1 = rotl32(x1, 15); x1 ^= x0;
    x0 += x1; x1 = rotl32(x1, 26); x1 ^= x0;
    x0 += x1; x1 = rotl32(x1,  6); x1 ^= x0;
    x0 += ks2; x1 += k0 + 5u;
}

__device__ inline float tf_uniform(uint32_t k0, uint32_t k1, uint32_t f, uint32_t half_) {
    uint32_t sec = (f >= half_) ? 1u : 0u;
    uint32_t lane = sec ? (f - half_) : f;
    uint32_t x0 = lane, x1 = lane + half_;
    tf2x32(k0, k1, x0, x1);
    uint32_t bits = sec ? x1 : x0;
    return __uint_as_float((bits >> 9) | 0x3f800000u) - 1.0f;
}

__device__ inline void tf_uniform2(uint32_t k0, uint32_t k1, uint32_t f, uint32_t half_,
                                   float& u0, float& u1) {
    uint32_t x0 = f, x1 = f + half_;
    tf2x32(k0, k1, x0, x1);
    u0 = __uint_as_float((x0 >> 9) | 0x3f800000u) - 1.0f;
    u1 = __uint_as_float((x1 >> 9) | 0x3f800000u) - 1.0f;
}

__device__ inline float sigmoidf_(float x) {
    float e = expf(-fabsf(x));
    float s = 1.0f / (1.0f + e);
    return (x >= 0.0f) ? s : (1.0f - s);
}
__device__ inline float softplusf_(float x) {
    return fmaxf(x, 0.0f) + log1pf(expf(-fabsf(x)));
}

// ---------------- smem / mma helpers (baseline instructions only) ----------------
__device__ __forceinline__ uint32_t smem_u32(const void* p) {
    uint32_t a;
    asm("{ .reg .u64 t; cvta.to.shared.u64 t, %1; cvt.u32.u64 %0, t; }" : "=r"(a) : "l"(p));
    return a;
}
#define SWZ(o) ((o) ^ (((o) >> 3) & 0x70))

#define CP16(dst, src) \
    asm volatile("cp.async.cg.shared.global [%0], [%1], 16;" :: "r"(dst), "l"(src))
#define CPC() asm volatile("cp.async.commit_group;" ::: "memory")
template <int N> __device__ __forceinline__ void cp_wait() {
    asm volatile("cp.async.wait_group %0;" :: "n"(N) : "memory");
}

__device__ __forceinline__ void ldm4(uint32_t* r, uint32_t a) {
    asm volatile("ldmatrix.sync.aligned.m8n8.x4.shared.b16 {%0,%1,%2,%3}, [%4];"
        : "=r"(r[0]), "=r"(r[1]), "=r"(r[2]), "=r"(r[3]) : "r"(a));
}
__device__ __forceinline__ void mma16816(float* d, const uint32_t* a, const uint32_t* b) {
    asm volatile(
        "mma.sync.aligned.m16n8k16.row.col.f32.f16.f16.f32 "
        "{%0,%1,%2,%3}, {%4,%5,%6,%7}, {%8,%9}, {%0,%1,%2,%3};"
        : "+f"(d[0]), "+f"(d[1]), "+f"(d[2]), "+f"(d[3])
        : "r"(a[0]), "r"(a[1]), "r"(a[2]), "r"(a[3]), "r"(b[0]), "r"(b[1]));
}

__device__ __forceinline__ uint32_t pkh(float x, float y) {
    __half2 h = __floats2half2_rn(x, y);
    return *(uint32_t*)&h;
}
// exact fp16 2-way split: a ~= hi + half(lo), hi exact fp16 value as float
__device__ __forceinline__ void split2(float a, float& hi, float& lo) {
    hi = __half2float(__float2half_rn(a));
    lo = a - hi;
}

// ---------------- prep: fp16 splits + combined cond-param weights + Wsum ----------------
__global__ void __launch_bounds__(256) prep_kernel(
    const float* __restrict__ W, const float* __restrict__ b, const float* __restrict__ c,
    const float* __restrict__ fc2w, const float* __restrict__ fc2b)
{
    int idx = blockIdx.x * blockDim.x + threadIdx.x;
    int stride = gridDim.x * blockDim.x;
    for (int i = idx; i < 256 * 256; i += stride) {
        int n = i >> 8, k = i & 255;
        float w1 = W[k * 256 + n];
        float h1, l1; split2(w1, h1, l1);
        g_S1[0][i] = __float2half_rn(h1);
        g_S1[1][i] = __float2half_rn(l1);
        float w2 = W[n * 256 + k];
        float h2, l2; split2(w2, h2, l2);
        g_S2[0][i] = __float2half_rn(h2);
        g_S2[1][i] = __float2half_rn(l2);
    }
    for (int i = idx; i < 64 * 768; i += stride) {
        int k = i / 768, n = i % 768;
        float val;
        if (n < 256)      val = b[n] * fc2w[n * 64 + k] + fc2w[(256 + n) * 64 + k];
        else if (n < 512) { int j = n - 256; val = c[j] * fc2w[(512 + j) * 64 + k] + fc2w[(768 + j) * 64 + k]; }
        else              { int j = n - 512; val = fc2w[(1024 + j) * 64 + k]; }
        g_P[k * 768 + n] = val;
    }
    for (int i = idx; i < 768; i += stride) {
        float val;
        if (i < 256)      val = b[i] * (1.0f + fc2b[i]) + fc2b[256 + i];
        else if (i < 512) { int j = i - 256; val = c[j] * (1.0f + fc2b[512 + j]) + fc2b[768 + j]; }
        else              { int j = i - 512; val = fc2b[1024 + j]; }
        g_pb[i] = val;
    }
    for (int i = idx; i < 256; i += stride) {
        float s = 0.0f;
        for (int rr = 0; rr < 256; rr++) s += W[rr * 256 + i];
        g_Wsum[i] = s;
    }
}

// ---------------- cond fc1: x = tanh(cond @ fc1_w.T + fc1_b) ----------------
__global__ void __launch_bounds__(256) cond_fc1_kernel(
    const float* __restrict__ cond, const float* __restrict__ fc1w,
    const float* __restrict__ fc1b, float* __restrict__ xout)
{
    __shared__ float Cs[64][65];
    __shared__ float Ws[64][65];
    int t = threadIdx.x;
    int r0 = blockIdx.x * 64;
#pragma unroll
    for (int l = 0; l < 4; l++) {
        int id = t + l * 256;
        int j = id >> 4, k4 = (id & 15) << 2;
        float4 w = *(const float4*)(fc1w + j * 64 + k4);
        Ws[k4 + 0][j] = w.x; Ws[k4 + 1][j] = w.y; Ws[k4 + 2][j] = w.z; Ws[k4 + 3][j] = w.w;
    }
#pragma unroll
    for (int l = 0; l < 4; l++) {
        int id = t + l * 256;
        int i = id >> 4, k4 = (id & 15) << 2;
        float4 v = *(const float4*)(cond + (size_t)(r0 + i) * 64 + k4);
        Cs[i][k4 + 0] = v.x; Cs[i][k4 + 1] = v.y; Cs[i][k4 + 2] = v.z; Cs[i][k4 + 3] = v.w;
    }
    __syncthreads();
    int tx = t & 15, ty = t >> 4;
    float acc[4][4];
#pragma unroll
    for (int i = 0; i < 4; i++)
#pragma unroll
        for (int j = 0; j < 4; j++) acc[i][j] = 0.0f;
#pragma unroll 8
    for (int k = 0; k < 64; k++) {
        float a[4], bv[4];
#pragma unroll
        for (int i = 0; i < 4; i++) a[i] = Cs[ty * 4 + i][k];
#pragma unroll
        for (int j = 0; j < 4; j++) bv[j] = Ws[k][tx * 4 + j];
#pragma unroll
        for (int i = 0; i < 4; i++)
#pragma unroll
            for (int j = 0; j < 4; j++) acc[i][j] = fmaf(a[i], bv[j], acc[i][j]);
    }
#pragma unroll
    for (int i = 0; i < 4; i++) {
        int r = r0 + ty * 4 + i;
#pragma unroll
        for (int j = 0; j < 4; j++) {
            int jj = tx * 4 + j;
            xout[(size_t)r * 64 + jj] = tanhf(acc[i][j] + fc1b[jj]);
        }
    }
}

// ---------------- cond-param SGEMM (fp32, K=64, N=768) ----------------
__global__ void __launch_bounds__(256, 2) sgemm0_kernel(
    const float* __restrict__ A, const float* __restrict__ Bm,
    float* __restrict__ out, const float* __restrict__ pb, int M)
{
    __shared__ float As[16][132];
    __shared__ float Bs[16][128];
    const int t = threadIdx.x;
    const int tx = t & 15, ty = t >> 4;
    const int bx = blockIdx.x, by = blockIdx.y;
    const int N = 768, K = 64;
    const float* Ab = A + (size_t)by * 128 * K;
    const float* Bb = Bm + (size_t)bx * 128;
    float acc[8][8];
#pragma unroll
    for (int i = 0; i < 8; i++)
#pragma unroll
        for (int j = 0; j < 8; j++) acc[i][j] = 0.0f;
    for (int kb = 0; kb < K; kb += 16) {
#pragma unroll
        for (int l = 0; l < 2; l++) {
            int id = t + l * 256;
            int row = id >> 2, c4 = (id & 3) << 2;
            float4 va = *(const float4*)(Ab + (size_t)row * K + kb + c4);
            As[c4 + 0][row] = va.x; As[c4 + 1][row] = va.y;
            As[c4 + 2][row] = va.z; As[c4 + 3][row] = va.w;
        }
#pragma unroll
        for (int l = 0; l < 2; l++) {
            int id = t + l * 256;
            int kk = id >> 5, n4 = (id & 31) << 2;
            *(float4*)&Bs[kk][n4] = *(const float4*)(Bb + (size_t)(kb + kk) * N + n4);
        }
        __syncthreads();
#pragma unroll
        for (int kk = 0; kk < 16; kk++) {
            float a[8], bv[8];
#pragma unroll
            for (int i = 0; i < 8; i++) a[i] = As[kk][ty * 8 + i];
#pragma unroll
            for (int j = 0; j < 8; j++) bv[j] = Bs[kk][tx * 8 + j];
#pragma unroll
            for (int i = 0; i < 8; i++)
#pragma unroll
                for (int j = 0; j < 8; j++) acc[i][j] = fmaf(a[i], bv[j], acc[i][j]);
        }
        __syncthreads();
    }
#pragma unroll
    for (int i = 0; i < 8; i++) {
        int r = by * 128 + ty * 8 + i;
#pragma unroll
        for (int j = 0; j < 8; j++) {
            int c = bx * 128 + tx * 8 + j;
            float val = acc[i][j] + pb[c];
            if (c >= 512) val = 1.0f + 0.05f * tanhf(val);
            out[(size_t)(c >> 8) * M * 256 + (size_t)r * 256 + (c & 255)] = val;
        }
    }
}

// ---------------- init: vd16 = fp16(v_data); v16 = noise/copy ----------------
__global__ void __launch_bounds__(256) init_v_kernel(
    const float* __restrict__ vdata, __half* __restrict__ v16,
    __half* __restrict__ vd16, int B, int n_noise, uint32_t k0, uint32_t k1)
{
    int total = B * 256;
    uint32_t half_ = (uint32_t)(n_noise * 128);
    for (int idx = blockIdx.x * blockDim.x + threadIdx.x; idx < total;
         idx += gridDim.x * blockDim.x) {
        int r = idx >> 8;
        float vd = vdata[idx];
        vd16[idx] = __float2half_rn(vd);
        float val = vd;
        if (r < n_noise) {
            float u = tf_uniform(k0, k1, (uint32_t)idx, half_);
            val = (u < 0.5f) ? 1.0f : 0.0f;
        }
        v16[idx] = __float2half_rn(val);
    }
}

// ---------------- fp16 mma.sync GEMM, chunk-staged (M=128 split rows, N=128) ----------------
// MODE 1: h-sample -> ahi/alo (fp16 2-split of h?ws:0). A = {v16}, streams {A0B0, A0B1}.
// MODE 2: v-sample -> v16. A = {ahi, alo}, streams {A0B0, A0B1, A1B0}.
// MODE 3: plain fp32 store -> outf. A = {vd16 or v16}, streams {A0B0, A0B1}.
// smem: A0 @0, A1 @16384, B0 @32768, B1 @49152 (64 KB total, single buffer).
#define MG_SMEM 65536

template <int MODE>
__global__ void __launch_bounds__(256, 2) mma_gemm(
    const __half* __restrict__ A0, const __half* __restrict__ A1,
    const __half* __restrict__ B0, const __half* __restrict__ B1,
    const float* __restrict__ e0, const float* __restrict__ e1,
    float* __restrict__ outf,
    __half* __restrict__ o0, __half* __restrict__ o1,
    int Bn, uint32_t rk0, uint32_t rk1, uint32_t hlf)
{
    extern __shared__ char sm[];
    const uint32_t smb = smem_u32(sm);
    const int t = threadIdx.x;
    const int lane = t & 31;
    const int wid = t >> 5;
    const int wm = wid & 1, wn = wid >> 1;
    const int bx = blockIdx.x, by = blockIdx.y;
    const int Mh = Bn >> 1;
    constexpr int NA = (MODE == 2) ? 2 : 1;
    constexpr int NU = (NA + 2) * 4;   // 16B units per thread per chunk

    float acc[4][4][4];
#pragma unroll
    for (int j = 0; j < 4; j++)
#pragma unroll
        for (int n = 0; n < 4; n++)
#pragma unroll
            for (int q = 0; q < 4; q++) acc[j][n][q] = 0.0f;

    const int arow = lane & 15;
    const int acolb = (lane >> 4) * 16;
    const int brow = (lane & 7) + (lane >> 4) * 8;
    const int bcolb = ((lane >> 3) & 1) * 16;

    for (int chunk = 0; chunk < 4; chunk++) {
        const int kc = chunk * 64;
        if (chunk) __syncthreads();      // previous compute done with tiles
        // stage all tiles for this chunk: NA A-tiles then 2 B-tiles
#pragma unroll
        for (int i = 0; i < NU; i++) {
            int u = t + i * 256;
            int tile = u >> 10;
            int r = (u >> 3) & 127;
            int q = u & 7;
            if (tile < NA) {
                int gr = (r < 64) ? (by * 64 + r) : (Mh + by * 64 + (r - 64));
                const __half* src = ((tile == 0) ? A0 : A1) + (size_t)gr * 256 + kc + q * 8;
                CP16(smb + tile * 16384 + SWZ(r * 128 + q * 16), src);
            } else {
                int bt = tile - NA;
                const __half* src = ((bt == 0) ? B0 : B1) + (size_t)(bx * 128 + r) * 256 + kc + q * 8;
                CP16(smb + 32768 + bt * 16384 + SWZ(r * 128 + q * 16), src);
            }
        }
        CPC();
        cp_wait<0>();
        __syncthreads();

#pragma unroll
        for (int kk = 0; kk < 4; kk++) {
            uint32_t a[4][4];
            uint32_t bf[4][2];
            // A0 frags
#pragma unroll
            for (int j = 0; j < 4; j++)
                ldm4(a[j], smb + SWZ((wm * 16 + j * 32 + arow) * 128 + kk * 32 + acolb));
            // B0
#pragma unroll
            for (int nb = 0; nb < 2; nb++) {
                uint32_t r4[4];
                ldm4(r4, smb + 32768 + SWZ((wn * 32 + nb * 16 + brow) * 128 + kk * 32 + bcolb));
                bf[nb * 2][0] = r4[0]; bf[nb * 2][1] = r4[1];
                bf[nb * 2 + 1][0] = r4[2]; bf[nb * 2 + 1][1] = r4[3];
            }
#pragma unroll
            for (int j = 0; j < 4; j++)
#pragma unroll
                for (int n = 0; n < 4; n++)
                    mma16816(acc[j][n], a[j], bf[n]);
            // B1 (A0 frags still live)
#pragma unroll
            for (int nb = 0; nb < 2; nb++) {
                uint32_t r4[4];
                ldm4(r4, smb + 49152 + SWZ((wn * 32 + nb * 16 + brow) * 128 + kk * 32 + bcolb));
                bf[nb * 2][0] = r4[0]; bf[nb * 2][1] = r4[1];
                bf[nb * 2 + 1][0] = r4[2]; bf[nb * 2 + 1][1] = r4[3];
            }
#pragma unroll
            for (int j = 0; j < 4; j++)
#pragma unroll
                for (int n = 0; n < 4; n++)
                    mma16816(acc[j][n], a[j], bf[n]);
            if (MODE == 2) {
                // A1 x B0
#pragma unroll
                for (int j = 0; j < 4; j++)
                    ldm4(a[j], smb + 16384 + SWZ((wm * 16 + j * 32 + arow) * 128 + kk * 32 + acolb));
#pragma unroll
                for (int nb = 0; nb < 2; nb++) {
                    uint32_t r4[4];
                    ldm4(r4, smb + 32768 + SWZ((wn * 32 + nb * 16 + brow) * 128 + kk * 32 + bcolb));
                    bf[nb * 2][0] = r4[0]; bf[nb * 2][1] = r4[1];
                    bf[nb * 2 + 1][0] = r4[2]; bf[nb * 2 + 1][1] = r4[3];
                }
#pragma unroll
                for (int j = 0; j < 4; j++)
#pragma unroll
                    for (int n = 0; n < 4; n++)
                        mma16816(acc[j][n], a[j], bf[n]);
            }
        }
    }

    // epilogue: tiles (j, j+2) pair rows (r, r+64) -> (gL, B/2+gL) for threefry pairing
    const int g = lane >> 2, t4 = lane & 3;
    const uint32_t cbase = (uint32_t)(bx * 128 + wn * 32 + t4 * 2);
#pragma unroll
    for (int j = 0; j < 2; j++)
#pragma unroll
    for (int hf = 0; hf < 2; hf++) {
        int tr = wm * 16 + j * 32 + g + hf * 8;          // 0..63
        uint32_t rowL = (uint32_t)(by * 64 + tr) * 256u;
#pragma unroll
        for (int n = 0; n < 4; n++) {
            uint32_t iL = rowL + cbase + n * 8;
            uint32_t iH = iL + hlf;
            float vL0 = acc[j][n][hf * 2 + 0], vL1 = acc[j][n][hf * 2 + 1];
            float vH0 = acc[j + 2][n][hf * 2 + 0], vH1 = acc[j + 2][n][hf * 2 + 1];
            if (MODE == 3) {
                *(float2*)(outf + iL) = make_float2(vL0, vL1);
                *(float2*)(outf + iH) = make_float2(vH0, vH1);
            } else {
                float u0, u1, u2, u3;
                tf_uniform2(rk0, rk1, iL, hlf, u0, u1);
                tf_uniform2(rk0, rk1, iL + 1, hlf, u2, u3);
                if (MODE == 1) {
                    float2 wsL = *(const float2*)(e0 + iL), wsH = *(const float2*)(e0 + iH);
                    float2 cmL = *(const float2*)(e1 + iL), cmH = *(const float2*)(e1 + iH);
                    float a00 = (u0 < sigmoidf_(fmaf(vL0, wsL.x, cmL.x))) ? wsL.x : 0.0f;
                    float a01 = (u2 < sigmoidf_(fmaf(vL1, wsL.y, cmL.y))) ? wsL.y : 0.0f;
                    float a10 = (u1 < sigmoidf_(fmaf(vH0, wsH.x, cmH.x))) ? wsH.x : 0.0f;
                    float a11 = (u3 < sigmoidf_(fmaf(vH1, wsH.y, cmH.y))) ? wsH.y : 0.0f;
                    float h0, l0, h1, l1, h2, l2, h3, l3;
                    split2(a00, h0, l0); split2(a01, h1, l1);
                    split2(a10, h2, l2); split2(a11, h3, l3);
                    *(uint32_t*)(o0 + iL) = pkh(h0, h1); *(uint32_t*)(o0 + iH) = pkh(h2, h3);
                    *(uint32_t*)(o1 + iL) = pkh(l0, l1); *(uint32_t*)(o1 + iH) = pkh(l2, l3);
                } else {
                    float2 bmL = *(const float2*)(e0 + iL), bmH = *(const float2*)(e0 + iH);
                    float b00 = (u0 < sigmoidf_(vL0 + bmL.x)) ? 1.0f : 0.0f;
                    float b01 = (u2 < sigmoidf_(vL1 + bmL.y)) ? 1.0f : 0.0f;
                    float b10 = (u1 < sigmoidf_(vH0 + bmH.x)) ? 1.0f : 0.0f;
                    float b11 = (u3 < sigmoidf_(vH1 + bmH.y)) ? 1.0f : 0.0f;
                    *(uint32_t*)(o0 + iL) = pkh(b00, b01);
                    *(uint32_t*)(o0 + iH) = pkh(b10, b11);
                }
            }
        }
    }
}

// ---------------- free-energy reduce ----------------
template <int VB>
__global__ void __launch_bounds__(256) fe_reduce_kernel(
    const float* __restrict__ vw, const float* __restrict__ vf,
    const __half* __restrict__ vb,
    const float* __restrict__ bmod, const float* __restrict__ cmod,
    const float* __restrict__ ws, const float* __restrict__ Wsum,
    float sign, float* __restrict__ part, int partBase)
{
    __shared__ float sW[256];
    __shared__ float wres[8];
    int t = threadIdx.x;
    sW[t] = Wsum[t];
    __syncthreads();
    int warp = t >> 5, lane = t & 31;
    int r = blockIdx.x * 8 + warp;
    size_t base = (size_t)r * 256;
    float s2v = 0.0f, s2f = 0.0f, s1v = 0.0f, s1f = 0.0f;
#pragma unroll
    for (int jj = 0; jj < 8; jj++) {
        int c = jj * 32 + lane;
        float tt = vw[base + c];
        float w  = ws[base + c];
        float cm = cmod[base + c];
        float tv = tt * w;
        s2v += softplusf_(tv + cm);
        s2f += softplusf_(fmaf(sW[c], w, cm) - tv);
        float bm = bmod[base + c];
        float vv = VB ? __half2float(vb[base + c]) : vf[base + c];
        s1v = fmaf(vv, bm, s1v);
        s1f = fmaf(1.0f - vv, bm, s1f);
    }
#pragma unroll
    for (int o = 16; o > 0; o >>= 1) {
        s2v += __shfl_xor_sync(0xffffffffu, s2v, o);
        s2f += __shfl_xor_sync(0xffffffffu, s2f, o);
        s1v += __shfl_xor_sync(0xffffffffu, s1v, o);
        s1f += __shfl_xor_sync(0xffffffffu, s1f, o);
    }
    if (lane == 0) {
        float av = s1v + s2v;
        float af = s1f + s2f;
        float mx = fmaxf(av, af);
        wres[warp] = sign * (-(mx + log1pf(expf(-fabsf(av - af)))));
    }
    __syncthreads();
    if (t == 0) {
        float s = 0.0f;
#pragma unroll
        for (int w = 0; w < 8; w++) s += wres[w];
        part[partBase + blockIdx.x] = s;
    }
}

__global__ void __launch_bounds__(256) final_reduce_kernel(
    const float* __restrict__ part, int n, float invB, float* __restrict__ out)
{
    __shared__ float s[256];
    float acc = 0.0f;
    for (int i = threadIdx.x; i < n; i += 256) acc += part[i];
    s[threadIdx.x] = acc;
    __syncthreads();
    for (int o = 128; o > 0; o >>= 1) {
        if (threadIdx.x < o) s[threadIdx.x] += s[threadIdx.x + o];
        __syncthreads();
    }
    if (threadIdx.x == 0) out[0] = s[0] * invB;
}

// ---------------- host: JAX key chain ----------------
static inline void host_split2(uint32_t k0, uint32_t k1, uint32_t* ka, uint32_t* kb) {
    uint32_t a0 = 0, b0 = 2; tf2x32(k0, k1, a0, b0);
    uint32_t a1 = 1, b1 = 3; tf2x32(k0, k1, a1, b1);
    ka[0] = a0; ka[1] = a1; kb[0] = b0; kb[1] = b1;
}
static inline void host_split3(uint32_t k0, uint32_t k1,
                               uint32_t* kA, uint32_t* kB, uint32_t* kC) {
    uint32_t a0 = 0, b0 = 3; tf2x32(k0, k1, a0, b0);
    uint32_t a1 = 1, b1 = 4; tf2x32(k0, k1, a1, b1);
    uint32_t a2 = 2, b2 = 5; tf2x32(k0, k1, a2, b2);
    kA[0] = a0; kA[1] = a1;
    kB[0] = a2; kB[1] = b0;
    kC[0] = b1; kC[1] = b2;
}

extern "C" void kernel_launch(void* const* d_in, const int* in_sizes, int n_in,
                              void* d_out, int out_size)
{
    const float* v_data = (const float*)d_in[0];
    const float* cond   = (const float*)d_in[1];
    const float* W      = (const float*)d_in[2];
    const float* b      = (const float*)d_in[3];
    const float* c      = (const float*)d_in[4];
    const float* fc1w   = (const float*)d_in[5];
    const float* fc1b   = (const float*)d_in[6];
    const float* fc2w   = (const float*)d_in[7];
    const float* fc2b   = (const float*)d_in[8];

    int B = in_sizes[0] / 256;
    if (B > BMAX) B = BMAX;
    int n_noise = (int)((double)B * 0.1);

    cudaFuncSetAttribute(mma_gemm<1>, cudaFuncAttributeMaxDynamicSharedMemorySize, MG_SMEM);
    cudaFuncSetAttribute(mma_gemm<2>, cudaFuncAttributeMaxDynamicSharedMemorySize, MG_SMEM);
    cudaFuncSetAttribute(mma_gemm<3>, cudaFuncAttributeMaxDynamicSharedMemorySize, MG_SMEM);

    float *p_x, *p_cond, *p_t, *p_Wsum, *p_part, *p_P, *p_pb;
    __half *p_v16, *p_vd16, *p_ahi, *p_alo, *p_S1, *p_S2;
    cudaGetSymbolAddress((void**)&p_x,    g_x);
    cudaGetSymbolAddress((void**)&p_cond, g_cond);
    cudaGetSymbolAddress((void**)&p_t,    g_t);
    cudaGetSymbolAddress((void**)&p_Wsum, g_Wsum);
    cudaGetSymbolAddress((void**)&p_part, g_part);
    cudaGetSymbolAddress((void**)&p_P,    g_P);
    cudaGetSymbolAddress((void**)&p_pb,   g_pb);
    cudaGetSymbolAddress((void**)&p_v16,  g_v16);
    cudaGetSymbolAddress((void**)&p_vd16, g_vd16);
    cudaGetSymbolAddress((void**)&p_ahi,  g_ahi);
    cudaGetSymbolAddress((void**)&p_alo,  g_alo);
    cudaGetSymbolAddress((void**)&p_S1,   g_S1);
    cudaGetSymbolAddress((void**)&p_S2,   g_S2);
    float* p_bmod = p_cond;
    float* p_cmod = p_cond + (size_t)B * 256;
    float* p_ws   = p_cond + (size_t)2 * B * 256;
    __half* S1a = p_S1; __half* S1b = p_S1 + 65536;
    __half* S2a = p_S2; __half* S2b = p_S2 + 65536;

    uint32_t rng[2] = {0u, 42u};
    uint32_t kn[2];
    host_split2(rng[0], rng[1], rng, kn);
    uint32_t k1s[5][2], k2s[5][2];
    for (int s = 0; s < 5; s++) {
        uint32_t nk[2];
        host_split3(rng[0], rng[1], nk, k1s[s], k2s[s]);
        rng[0] = nk[0]; rng[1] = nk[1];
    }

    prep_kernel<<<128, 256>>>(W, b, c, fc2w, fc2b);
    cond_fc1_kernel<<<B / 64, 256>>>(cond, fc1w, fc1b, p_x);
    dim3 g0(6, B / 128);
    sgemm0_kernel<<<g0, 256>>>(p_x, p_P, p_cond, p_pb, B);
    init_v_kernel<<<2048, 256>>>(v_data, p_v16, p_vd16, B, n_noise, kn[0], kn[1]);

    uint32_t hlf = (uint32_t)B * 128u;
    dim3 gmm(2, B / 128);
    for (int s = 0; s < 5; s++) {
        mma_gemm<1><<<gmm, 256, MG_SMEM>>>(p_v16, nullptr,
                                           S1a, S1b,
                                           p_ws, p_cmod, nullptr,
                                           p_ahi, p_alo,
                                           B, k1s[s][0], k1s[s][1], hlf);
        mma_gemm<2><<<gmm, 256, MG_SMEM>>>(p_ahi, p_alo,
                                           S2a, S2b,
                                           p_bmod, nullptr, nullptr,
                                           p_v16, nullptr,
                                           B, k2s[s][0], k2s[s][1], hlf);
    }

    mma_gemm<3><<<gmm, 256, MG_SMEM>>>(p_vd16, nullptr,
                                       S1a, S1b,
                                       nullptr, nullptr, p_t,
                                       nullptr, nullptr,
                                       B, 0u, 0u, hlf);
    fe_reduce_kernel<0><<<B / 8, 256>>>(p_t, v_data, nullptr, p_bmod, p_cmod, p_ws,
                                        p_Wsum, 1.0f, p_part, 0);
    mma_gemm<3><<<gmm, 256, MG_SMEM>>>(p_v16, nullptr,
                                       S1a, S1b,
                                       nullptr, nullptr, p_t,
                                       nullptr, nullptr,
                                       B, 0u, 0u, hlf);
    fe_reduce_kernel<1><<<B / 8, 256>>>(p_t, nullptr, p_v16, p_bmod, p_cmod, p_ws,
                                        p_Wsum, -1.0f, p_part, B / 8);

    final_reduce_kernel<<<1, 256>>>(p_part, 2 * (B / 8), 1.0f / (float)B, (float*)d_out);
}